// round 11
// baseline (speedup 1.0000x reference)
#include <cuda_runtime.h>
#include <cstdint>

#define H       64
#define K       256
#define TILE_M  64
#define TPB     256
#define MARGIN  1.75f
#define BFS     176                      // bf16 row stride in bytes (88 halves; 80 used)
#define FLT_INF 3.402823466e+38f
#define QMAX    2048

// ---- dynamic smem layout (bytes) ----
#define OFF_CBF   0                      // B = bf16(-2c | c2): 256 * 176 = 45056
#define OFF_XBF   45056                  // A = bf16(x | 1):    64 * 176  = 11264
#define OFF_XF32  56320                  // X fp32 double buffer: 2 * 16384
#define OFF_C2    89088                  // ||c||^2 fp32 (exact, for rescore): 256*4
#define OFF_RMIN  90112                  // row partial mins: 64 * 2 * 4
#define OFF_RES   90624                  // packed (d2,k) per row: 64 * 8
#define OFF_Q     91136                  // candidate queue: 2048 * 4
#define OFF_QN    99328                  // queue counter
#define OFF_OFL   99344                  // per-row overflow flags: 64 * 4
#define OFF_RCNT  99600                  // per-row candidate count: 64 * 4
#define OFF_RK1   99856                  // per-row single candidate k: 64 * 4
#define SMEM_TOTAL 100352

__device__ __forceinline__ uint32_t smem_u32(const void* p) {
    uint32_t a;
    asm("{ .reg .u64 t; cvta.to.shared.u64 t, %1; cvt.u32.u64 %0, t; }" : "=r"(a) : "l"(p));
    return a;
}

__device__ __forceinline__ uint32_t bf16x2_pack(float lo, float hi) {
    uint32_t r;
    asm("cvt.rn.bf16x2.f32 %0, %1, %2;" : "=r"(r) : "f"(hi), "f"(lo));
    return r;
}

__device__ __forceinline__ void ldsm4(uint32_t* r, uint32_t addr) {
    asm volatile("ldmatrix.sync.aligned.m8n8.x4.shared.b16 {%0,%1,%2,%3}, [%4];"
        : "=r"(r[0]), "=r"(r[1]), "=r"(r[2]), "=r"(r[3]) : "r"(addr));
}

__device__ __forceinline__ void mma_bf16(float* d, const uint32_t* a, const uint32_t* b) {
    asm volatile("mma.sync.aligned.m16n8k16.row.col.f32.bf16.bf16.f32 "
        "{%0,%1,%2,%3}, {%4,%5,%6,%7}, {%8,%9}, {%0,%1,%2,%3};"
        : "+f"(d[0]), "+f"(d[1]), "+f"(d[2]), "+f"(d[3])
        : "r"(a[0]), "r"(a[1]), "r"(a[2]), "r"(a[3]), "r"(b[0]), "r"(b[1]));
}

__device__ __forceinline__ void cp16(uint32_t dst, const void* src) {
    asm volatile("cp.async.cg.shared.global [%0], [%1], 16;" :: "r"(dst), "l"(src));
}

// exact rescore (sequential-h fp32, float4 loads), monotone-packed (d2,k)
__device__ __forceinline__ unsigned long long rescore_pack(const float* __restrict__ xr,
                                                           const float* __restrict__ crow,
                                                           float c2k, int k) {
    float x2 = 0.f, dot = 0.f;
    #pragma unroll
    for (int h4 = 0; h4 < H / 4; ++h4) {
        float4 xv = *(const float4*)(xr + h4 * 4);
        float4 cv = __ldg((const float4*)(crow + h4 * 4));
        x2 = __fadd_rn(x2, __fmul_rn(xv.x, xv.x));
        dot = __fmaf_rn(xv.x, cv.x, dot);
        x2 = __fadd_rn(x2, __fmul_rn(xv.y, xv.y));
        dot = __fmaf_rn(xv.y, cv.y, dot);
        x2 = __fadd_rn(x2, __fmul_rn(xv.z, xv.z));
        dot = __fmaf_rn(xv.z, cv.z, dot);
        x2 = __fadd_rn(x2, __fmul_rn(xv.w, xv.w));
        dot = __fmaf_rn(xv.w, cv.w, dot);
    }
    float d2 = __fmaf_rn(-2.f, dot, __fadd_rn(x2, c2k));
    uint32_t b = __float_as_uint(d2);
    b ^= (b & 0x80000000u) ? 0xFFFFFFFFu : 0x80000000u;    // monotone map
    return ((unsigned long long)b << 32) | (unsigned)k;
}

extern __shared__ char smem_raw[];

__global__ __launch_bounds__(TPB, 2)
void LatentSpaceClustering_46797963657837_kernel(const float* __restrict__ x,
                                                 const float* __restrict__ c,
                                                 float* __restrict__ out,
                                                 int n, int num_tiles) {
    const uint32_t sbase = smem_u32(smem_raw);
    float* c2f  = (float*)(smem_raw + OFF_C2);
    float* rmin = (float*)(smem_raw + OFF_RMIN);
    unsigned long long* res = (unsigned long long*)(smem_raw + OFF_RES);
    uint32_t* q    = (uint32_t*)(smem_raw + OFF_Q);
    int*      qn   = (int*)(smem_raw + OFF_QN);
    int*      ofl  = (int*)(smem_raw + OFF_OFL);
    int*      rcnt = (int*)(smem_raw + OFF_RCNT);
    int*      rk1  = (int*)(smem_raw + OFF_RK1);
    const int tid = threadIdx.x;
    const int lane = tid & 31, w = tid >> 5;
    const int groupID = lane >> 2, tig = lane & 3;
    const int mtile = w & 3, half = w >> 2;
    const int hbase = half * 128;

    // ---- stage B = bf16(-2c) rows (h<64) ----
    {
        const float4* c4 = (const float4*)c;
        for (int j = tid; j < K * H / 4; j += TPB) {
            float4 v = c4[j];
            int k = j >> 4, h = (j & 15) << 2;
            uint2 p = make_uint2(bf16x2_pack(-2.f * v.x, -2.f * v.y),
                                 bf16x2_pack(-2.f * v.z, -2.f * v.w));
            *(uint2*)(smem_raw + OFF_CBF + k * BFS + h * 2) = p;
        }
    }
    // ---- exact ||c_k||^2 (fp32 sequential, reference-style) + B k4 row ----
    {
        int k = tid;                                          // TPB == K
        const float* cr = c + k * H;
        float s = 0.f;
        #pragma unroll 8
        for (int h = 0; h < H; ++h) {
            float v = __ldg(cr + h);
            s = __fadd_rn(s, __fmul_rn(v, v));
        }
        c2f[k] = s;
        // B[k][h=64] = bf16(c2), h=65..79 = 0
        uint4 z = make_uint4(0u, 0u, 0u, 0u);
        uint4 p0 = make_uint4(bf16x2_pack(s, 0.f), 0u, 0u, 0u);
        *(uint4*)(smem_raw + OFF_CBF + k * BFS + 128) = p0;
        *(uint4*)(smem_raw + OFF_CBF + k * BFS + 144) = z;
    }
    // ---- A ones-row (h=64 -> 1, h=65..79 -> 0), constant across tiles ----
    if (tid < 128) {
        int row = tid >> 1, sel = tid & 1;
        uint4 v = make_uint4(0u, 0u, 0u, 0u);
        if (sel == 0) v.x = bf16x2_pack(1.f, 0.f);
        *(uint4*)(smem_raw + OFF_XBF + row * BFS + 128 + sel * 16) = v;
    }

    // ---- prefetch first tile (buf 0): 64 rows * 256B = 1024 x 16B ----
    int buf = 0;
    {
        long long base_pt = (long long)blockIdx.x * TILE_M;
        #pragma unroll
        for (int i = 0; i < 4; ++i) {
            int chunk = i * TPB + tid;
            int row = chunk >> 4, seg = chunk & 15;
            if (base_pt + row < n)
                cp16(sbase + OFF_XF32 + chunk * 16, x + (base_pt + row) * H + seg * 4);
        }
        asm volatile("cp.async.commit_group;");
    }

    const uint32_t a_base = sbase + OFF_XBF + (mtile * 16 + (lane & 15)) * BFS + ((lane >> 4) * 16);
    // ldsm4 B: lanes 0-7 n-tile 2j khalf0, 8-15 2j khalf1, 16-23 2j+1 khalf0, 24-31 2j+1 khalf1
    const uint32_t b_base = sbase + OFF_CBF
        + (hbase + (lane & 7) + ((lane >> 4) << 3)) * BFS
        + (((lane >> 3) & 1) * 16);
    const int r0 = mtile * 16 + groupID, r1 = r0 + 8;

    for (int tile = blockIdx.x; tile < num_tiles; tile += gridDim.x) {
        const long long base_pt = (long long)tile * TILE_M;
        asm volatile("cp.async.wait_group 0;" ::: "memory");
        __syncthreads();

        // ---- convert fp32 -> bf16 padded; init per-tile state ----
        const float* xf = (const float*)(smem_raw + OFF_XF32 + buf * 16384);
        #pragma unroll
        for (int i = 0; i < 4; ++i) {
            int idx = i * TPB + tid;
            int row = idx >> 4, h = (idx & 15) << 2;
            const float* r = xf + row * H + h;
            uint2 p = make_uint2(bf16x2_pack(r[0], r[1]), bf16x2_pack(r[2], r[3]));
            *(uint2*)(smem_raw + OFF_XBF + row * BFS + h * 2) = p;
        }
        if (tid < TILE_M) {
            res[tid] = 0xFFFFFFFFFFFFFFFFull;
            ofl[tid] = 0;
            rcnt[tid] = 0;
        }
        if (tid == 0) *qn = 0;
        __syncthreads();

        // ---- prefetch next tile into other buffer ----
        {
            long long nb = (long long)(tile + gridDim.x) * TILE_M;
            if (tile + gridDim.x < num_tiles) {
                #pragma unroll
                for (int i = 0; i < 4; ++i) {
                    int chunk = i * TPB + tid;
                    int row = chunk >> 4, seg = chunk & 15;
                    if (nb + row < n)
                        cp16(sbase + OFF_XF32 + (buf ^ 1) * 16384 + chunk * 16,
                             x + (nb + row) * H + seg * 4);
                }
            }
            asm volatile("cp.async.commit_group;");
        }

        // ---- mma: acc = c2 - 2*x.c directly (5 k-steps incl. augmented) ----
        float acc[64];
        #pragma unroll
        for (int j = 0; j < 64; ++j) acc[j] = 0.f;
        uint32_t a[5][4];
        #pragma unroll
        for (int ks = 0; ks < 5; ++ks) ldsm4(a[ks], a_base + ks * 32);

        uint32_t bb[2][4];
        ldsm4(bb[0], b_base);
        #pragma unroll
        for (int it = 0; it < 40; ++it) {        // it = ks*8 + jpair
            int cur = it & 1;
            if (it < 39) {
                int nx = it + 1;
                ldsm4(bb[cur ^ 1], b_base + (nx & 7) * (16 * BFS) + (nx >> 3) * 32);
            }
            int jp = it & 7, ks = it >> 3;
            mma_bf16(acc + (jp * 2) * 4,     a[ks], bb[cur]);
            mma_bf16(acc + (jp * 2 + 1) * 4, a[ks], bb[cur] + 2);
        }

        // ---- pass 1: per-row min (acc already = screening score) ----
        float mn0 = FLT_INF, mn1 = FLT_INF;
        #pragma unroll
        for (int j = 0; j < 16; ++j) {
            mn0 = fminf(mn0, fminf(acc[j*4+0], acc[j*4+1]));
            mn1 = fminf(mn1, fminf(acc[j*4+2], acc[j*4+3]));
        }
        #pragma unroll
        for (int off = 1; off <= 2; off <<= 1) {
            mn0 = fminf(mn0, __shfl_xor_sync(0xffffffffu, mn0, off));
            mn1 = fminf(mn1, __shfl_xor_sync(0xffffffffu, mn1, off));
        }
        if (tig == 0) { rmin[r0 * 2 + half] = mn0; rmin[r1 * 2 + half] = mn1; }
        __syncthreads();

        // ---- pass 2: screen vs global row threshold ----
        const float thr0 = fminf(rmin[r0 * 2], rmin[r0 * 2 + 1]) + MARGIN;
        const float thr1 = fminf(rmin[r1 * 2], rmin[r1 * 2 + 1]) + MARGIN;
        #pragma unroll
        for (int j = 0; j < 16; ++j) {
            #pragma unroll
            for (int e = 0; e < 2; ++e) {
                int k = hbase + j * 8 + tig * 2 + e;
                if (acc[j*4+e] < thr0) {
                    atomicAdd(&rcnt[r0], 1);
                    rk1[r0] = k;
                    int idx = atomicAdd(qn, 1);
                    if (idx < QMAX) q[idx] = ((uint32_t)r0 << 8) | (uint32_t)k;
                    else ofl[r0] = 1;
                }
                if (acc[j*4+2+e] < thr1) {
                    atomicAdd(&rcnt[r1], 1);
                    rk1[r1] = k;
                    int idx = atomicAdd(qn, 1);
                    if (idx < QMAX) q[idx] = ((uint32_t)r1 << 8) | (uint32_t)k;
                    else ofl[r1] = 1;
                }
            }
        }
        __syncthreads();

        // ---- single-candidate fast path: that candidate IS the argmin ----
        if (tid < TILE_M && rcnt[tid] == 1)
            res[tid] = (unsigned)rk1[tid];      // high word 0 < any packed d2

        // ---- parallel exact rescore only for multi-candidate rows ----
        {
            int total = *qn;
            if (total > QMAX) total = QMAX;
            for (int i = tid; i < total; i += TPB) {
                uint32_t e = q[i];
                int row = e >> 8, k = e & 255;
                if (rcnt[row] > 1)
                    atomicMin(&res[row],
                              rescore_pack(xf + row * H, c + (size_t)k * H, c2f[k], k));
            }
        }
        // overflow fallback (pathological only)
        if (tid < TILE_M && ofl[tid]) {
            for (int k = 0; k < K; ++k)
                atomicMin(&res[tid],
                          rescore_pack(xf + tid * H, c + (size_t)k * H, c2f[k], k));
        }
        __syncthreads();

        // ---- write back ----
        if (tid < TILE_M) {
            long long g = base_pt + tid;
            if (g < n) out[g] = (float)(uint32_t)(res[tid] & 0xFFFFFFFFull);
        }

        buf ^= 1;
    }
}

extern "C" void kernel_launch(void* const* d_in, const int* in_sizes, int n_in,
                              void* d_out, int out_size) {
    const float* x = (const float*)d_in[0];
    const float* c = (const float*)d_in[1];
    int n = in_sizes[0] / H;
    int num_tiles = (n + TILE_M - 1) / TILE_M;

    int sms = 148;
    cudaDeviceGetAttribute(&sms, cudaDevAttrMultiProcessorCount, 0);

    cudaFuncSetAttribute(LatentSpaceClustering_46797963657837_kernel,
                         cudaFuncAttributeMaxDynamicSharedMemorySize, SMEM_TOTAL);

    int grid = 2 * sms;
    if (grid > num_tiles) grid = num_tiles;
    LatentSpaceClustering_46797963657837_kernel<<<grid, TPB, SMEM_TOTAL>>>(
        x, c, (float*)d_out, n, num_tiles);
}

// round 12
// speedup vs baseline: 1.4258x; 1.4258x over previous
#include <cuda_runtime.h>
#include <cstdint>

#define H       64
#define K       256
#define TILE_M  64
#define TPB     256
#define MARGIN  0.75f
#define BFS     144                      // bf16 row stride in bytes
#define FLT_INF 3.402823466e+38f
#define QMAXP   512                      // queue entries per pair

// ---- dynamic smem layout (bytes) ----
#define OFF_CBF   0                      // C bf16: 256*144 = 36864
#define OFF_XBF   36864                  // X bf16: 64*144 = 9216
#define OFF_XF32  46080                  // per-pair double buf: 4 * 2 * 4096 = 32768
#define OFF_C2    78848                  // ||c||^2 fp32: 256*4 (pad 1024)
#define OFF_RMINH 79872                  // row half-mins: 64*2*4 = 512
#define OFF_RES   80384                  // packed (d2,k) per row: 64*8 = 512
#define OFF_Q     80896                  // 4 pairs * 512 * 4 = 8192
#define OFF_QN    89088                  // 4 counters, 32B apart
#define OFF_OFL   89216                  // 64*4
#define OFF_RCNT  89472                  // 64*4
#define OFF_RK1   89728                  // 64*4
#define SMEM_TOTAL 89984

#define PBAR(p) asm volatile("bar.sync %0, 64;" :: "r"((p) + 1) : "memory")

__device__ __forceinline__ uint32_t smem_u32(const void* p) {
    uint32_t a;
    asm("{ .reg .u64 t; cvta.to.shared.u64 t, %1; cvt.u32.u64 %0, t; }" : "=r"(a) : "l"(p));
    return a;
}

__device__ __forceinline__ uint32_t bf16x2_pack(float lo, float hi) {
    uint32_t r;
    asm("cvt.rn.bf16x2.f32 %0, %1, %2;" : "=r"(r) : "f"(hi), "f"(lo));
    return r;
}

__device__ __forceinline__ void ldsm4(uint32_t* r, uint32_t addr) {
    asm volatile("ldmatrix.sync.aligned.m8n8.x4.shared.b16 {%0,%1,%2,%3}, [%4];"
        : "=r"(r[0]), "=r"(r[1]), "=r"(r[2]), "=r"(r[3]) : "r"(addr));
}

__device__ __forceinline__ void mma_bf16(float* d, const uint32_t* a, const uint32_t* b) {
    asm volatile("mma.sync.aligned.m16n8k16.row.col.f32.bf16.bf16.f32 "
        "{%0,%1,%2,%3}, {%4,%5,%6,%7}, {%8,%9}, {%0,%1,%2,%3};"
        : "+f"(d[0]), "+f"(d[1]), "+f"(d[2]), "+f"(d[3])
        : "r"(a[0]), "r"(a[1]), "r"(a[2]), "r"(a[3]), "r"(b[0]), "r"(b[1]));
}

__device__ __forceinline__ void cp16(uint32_t dst, const void* src) {
    asm volatile("cp.async.cg.shared.global [%0], [%1], 16;" :: "r"(dst), "l"(src));
}

// exact rescore (sequential-h fp32, float4 loads), monotone-packed (d2,k)
__device__ __forceinline__ unsigned long long rescore_pack(const float* __restrict__ xr,
                                                           const float* __restrict__ crow,
                                                           float c2k, int k) {
    float x2 = 0.f, dot = 0.f;
    #pragma unroll
    for (int h4 = 0; h4 < H / 4; ++h4) {
        float4 xv = *(const float4*)(xr + h4 * 4);
        float4 cv = __ldg((const float4*)(crow + h4 * 4));
        x2 = __fadd_rn(x2, __fmul_rn(xv.x, xv.x));
        dot = __fmaf_rn(xv.x, cv.x, dot);
        x2 = __fadd_rn(x2, __fmul_rn(xv.y, xv.y));
        dot = __fmaf_rn(xv.y, cv.y, dot);
        x2 = __fadd_rn(x2, __fmul_rn(xv.z, xv.z));
        dot = __fmaf_rn(xv.z, cv.z, dot);
        x2 = __fadd_rn(x2, __fmul_rn(xv.w, xv.w));
        dot = __fmaf_rn(xv.w, cv.w, dot);
    }
    float d2 = __fmaf_rn(-2.f, dot, __fadd_rn(x2, c2k));
    uint32_t b = __float_as_uint(d2);
    b ^= (b & 0x80000000u) ? 0xFFFFFFFFu : 0x80000000u;    // monotone map
    return ((unsigned long long)b << 32) | (unsigned)k;
}

extern __shared__ char smem_raw[];

__global__ __launch_bounds__(TPB, 2)
void LatentSpaceClustering_46797963657837_kernel(const float* __restrict__ x,
                                                 const float* __restrict__ c,
                                                 float* __restrict__ out,
                                                 int n, int num_tiles) {
    const uint32_t sbase = smem_u32(smem_raw);
    float* c2f  = (float*)(smem_raw + OFF_C2);
    float* rmin = (float*)(smem_raw + OFF_RMINH);
    unsigned long long* res = (unsigned long long*)(smem_raw + OFF_RES);
    int* ofl  = (int*)(smem_raw + OFF_OFL);
    int* rcnt = (int*)(smem_raw + OFF_RCNT);
    int* rk1  = (int*)(smem_raw + OFF_RK1);
    const int tid = threadIdx.x;
    const int lane = tid & 31, w = tid >> 5;
    const int groupID = lane >> 2, tig = lane & 3;
    const int pr = w & 3, half = w >> 2;          // pair id, n-half
    const int pairtid = half * 32 + lane;          // 0..63 within pair
    const int hbase = half * 128;

    uint32_t* qp  = (uint32_t*)(smem_raw + OFF_Q) + pr * QMAXP;
    int*      qnp = (int*)(smem_raw + OFF_QN + pr * 32);

    // ---- stage centers bf16 (padded rows) ----
    {
        const float4* c4 = (const float4*)c;
        for (int j = tid; j < K * H / 4; j += TPB) {
            float4 v = c4[j];
            int k = j >> 4, h = (j & 15) << 2;
            uint2 p = make_uint2(bf16x2_pack(v.x, v.y), bf16x2_pack(v.z, v.w));
            *(uint2*)(smem_raw + OFF_CBF + k * BFS + h * 2) = p;
        }
    }
    // ---- exact ||c_k||^2 (fp32 sequential, reference-style) ----
    {
        int k = tid;                               // TPB == K
        const float* cr = c + k * H;
        float s = 0.f;
        #pragma unroll 8
        for (int h = 0; h < H; ++h) {
            float v = __ldg(cr + h);
            s = __fadd_rn(s, __fmul_rn(v, v));
        }
        c2f[k] = s;
    }
    __syncthreads();

    const uint32_t xf32p = sbase + OFF_XF32 + pr * 8192;   // pair fp32 area (2 bufs)

    // ---- first-tile prefetch (pair's own 16 rows) ----
    {
        long long gb = (long long)blockIdx.x * TILE_M + pr * 16;
        #pragma unroll
        for (int i = 0; i < 4; ++i) {
            int chunk = i * 64 + pairtid;          // 256 chunks of 16B
            int row = chunk >> 4, seg = chunk & 15;
            if (gb + row < n)
                cp16(xf32p + row * 256 + seg * 16, x + (gb + row) * H + seg * 4);
        }
        asm volatile("cp.async.commit_group;");
    }

    const uint32_t a_base = sbase + OFF_XBF + (pr * 16 + (lane & 15)) * BFS + ((lane >> 4) * 16);
    const uint32_t b_base = sbase + OFF_CBF
        + (hbase + (lane & 7) + ((lane >> 4) << 3)) * BFS
        + (((lane >> 3) & 1) * 16);
    const int r0 = pr * 16 + groupID, r1 = r0 + 8;  // tile-rows owned by this thread

    int buf = 0;
    for (int tile = blockIdx.x; tile < num_tiles; tile += gridDim.x) {
        const long long pbase = (long long)tile * TILE_M + pr * 16;
        asm volatile("cp.async.wait_group 0;" ::: "memory");
        PBAR(pr);

        // ---- convert fp32 -> bf16 (pair rows); init pair state ----
        const float* xf = (const float*)(smem_raw + OFF_XF32 + pr * 8192 + buf * 4096);
        #pragma unroll
        for (int i = 0; i < 4; ++i) {
            int idx = i * 64 + pairtid;            // 256 = 16 rows * 16 float4
            int row = idx >> 4, h4 = idx & 15;
            float4 v = ((const float4*)xf)[row * 16 + h4];
            uint2 p = make_uint2(bf16x2_pack(v.x, v.y), bf16x2_pack(v.z, v.w));
            *(uint2*)(smem_raw + OFF_XBF + (pr * 16 + row) * BFS + h4 * 8) = p;
        }
        if (half == 0 && lane < 16) {
            int rg = pr * 16 + lane;
            res[rg] = 0xFFFFFFFFFFFFFFFFull;
            ofl[rg] = 0;
            rcnt[rg] = 0;
        }
        if (half == 1 && lane == 0) *qnp = 0;
        PBAR(pr);

        // ---- prefetch next tile into other buffer ----
        {
            long long nb = (long long)(tile + gridDim.x) * TILE_M + pr * 16;
            if (tile + gridDim.x < num_tiles) {
                #pragma unroll
                for (int i = 0; i < 4; ++i) {
                    int chunk = i * 64 + pairtid;
                    int row = chunk >> 4, seg = chunk & 15;
                    if (nb + row < n)
                        cp16(xf32p + (buf ^ 1) * 4096 + row * 256 + seg * 16,
                             x + (nb + row) * H + seg * 4);
                }
            }
            asm volatile("cp.async.commit_group;");
        }

        // ---- mma: 16m x 128n per warp, 4 k-steps, B ldsm4 2-deep ----
        float acc[64];
        #pragma unroll
        for (int j = 0; j < 64; ++j) acc[j] = 0.f;
        uint32_t a[4][4];
        #pragma unroll
        for (int ks = 0; ks < 4; ++ks) ldsm4(a[ks], a_base + ks * 32);

        uint32_t bb[2][4];
        ldsm4(bb[0], b_base);
        #pragma unroll
        for (int it = 0; it < 32; ++it) {          // it = ks*8 + jpair
            int cur = it & 1;
            if (it < 31) {
                int nx = it + 1;
                ldsm4(bb[cur ^ 1], b_base + (nx & 7) * (16 * BFS) + (nx >> 3) * 32);
            }
            int jp = it & 7, ks = it >> 3;
            mma_bf16(acc + (jp * 2) * 4,     a[ks], bb[cur]);
            mma_bf16(acc + (jp * 2 + 1) * 4, a[ks], bb[cur] + 2);
        }

        // ---- transform to s = c2 - 2*dot, per-row partial min ----
        float mn0 = FLT_INF, mn1 = FLT_INF;
        #pragma unroll
        for (int j = 0; j < 16; ++j) {
            float2 c2v = *(const float2*)(c2f + hbase + j * 8 + tig * 2);
            float s0 = __fmaf_rn(-2.f, acc[j*4+0], c2v.x);
            float s1 = __fmaf_rn(-2.f, acc[j*4+1], c2v.y);
            float s2 = __fmaf_rn(-2.f, acc[j*4+2], c2v.x);
            float s3 = __fmaf_rn(-2.f, acc[j*4+3], c2v.y);
            acc[j*4+0] = s0; acc[j*4+1] = s1; acc[j*4+2] = s2; acc[j*4+3] = s3;
            mn0 = fminf(mn0, fminf(s0, s1));
            mn1 = fminf(mn1, fminf(s2, s3));
        }
        #pragma unroll
        for (int off = 1; off <= 2; off <<= 1) {
            mn0 = fminf(mn0, __shfl_xor_sync(0xffffffffu, mn0, off));
            mn1 = fminf(mn1, __shfl_xor_sync(0xffffffffu, mn1, off));
        }
        if (tig == 0) { rmin[r0 * 2 + half] = mn0; rmin[r1 * 2 + half] = mn1; }
        PBAR(pr);

        // ---- screen vs combined row threshold; push to pair queue ----
        const float thr0 = fminf(rmin[r0 * 2], rmin[r0 * 2 + 1]) + MARGIN;
        const float thr1 = fminf(rmin[r1 * 2], rmin[r1 * 2 + 1]) + MARGIN;
        #pragma unroll
        for (int j = 0; j < 16; ++j) {
            #pragma unroll
            for (int e = 0; e < 2; ++e) {
                int k = hbase + j * 8 + tig * 2 + e;
                if (acc[j*4+e] < thr0) {
                    atomicAdd(&rcnt[r0], 1);
                    rk1[r0] = k;
                    int idx = atomicAdd(qnp, 1);
                    if (idx < QMAXP) qp[idx] = ((uint32_t)groupID << 8) | (uint32_t)k;
                    else ofl[r0] = 1;
                }
                if (acc[j*4+2+e] < thr1) {
                    atomicAdd(&rcnt[r1], 1);
                    rk1[r1] = k;
                    int idx = atomicAdd(qnp, 1);
                    if (idx < QMAXP) qp[idx] = ((uint32_t)(groupID + 8) << 8) | (uint32_t)k;
                    else ofl[r1] = 1;
                }
            }
        }
        PBAR(pr);

        // ---- single-candidate fast path ----
        if (half == 0 && lane < 16) {
            int rg = pr * 16 + lane;
            if (rcnt[rg] == 1) res[rg] = (unsigned)rk1[rg];
        }
        // ---- pair-parallel exact rescore for multi-candidate rows ----
        {
            int total = *qnp;
            if (total > QMAXP) total = QMAXP;
            for (int i = pairtid; i < total; i += 64) {
                uint32_t e = qp[i];
                int rl = e >> 8, k = e & 255;
                int rg = pr * 16 + rl;
                if (rcnt[rg] > 1)
                    atomicMin(&res[rg],
                              rescore_pack(xf + rl * H, c + (size_t)k * H, c2f[k], k));
            }
        }
        // overflow fallback (pathological only)
        if (half == 0 && lane < 16) {
            int rg = pr * 16 + lane;
            if (ofl[rg]) {
                for (int k = 0; k < K; ++k)
                    atomicMin(&res[rg],
                              rescore_pack(xf + lane * H, c + (size_t)k * H, c2f[k], k));
            }
        }
        PBAR(pr);

        // ---- write back (pair rows) ----
        if (half == 0 && lane < 16) {
            long long g = pbase + lane;
            if (g < n) out[g] = (float)(uint32_t)(res[pr * 16 + lane] & 0xFFFFFFFFull);
        }

        buf ^= 1;
    }
}

extern "C" void kernel_launch(void* const* d_in, const int* in_sizes, int n_in,
                              void* d_out, int out_size) {
    const float* x = (const float*)d_in[0];
    const float* c = (const float*)d_in[1];
    int n = in_sizes[0] / H;
    int num_tiles = (n + TILE_M - 1) / TILE_M;

    int sms = 148;
    cudaDeviceGetAttribute(&sms, cudaDevAttrMultiProcessorCount, 0);

    cudaFuncSetAttribute(LatentSpaceClustering_46797963657837_kernel,
                         cudaFuncAttributeMaxDynamicSharedMemorySize, SMEM_TOTAL);

    int grid = 2 * sms;
    if (grid > num_tiles) grid = num_tiles;
    LatentSpaceClustering_46797963657837_kernel<<<grid, TPB, SMEM_TOTAL>>>(
        x, c, (float*)d_out, n, num_tiles);
}